// round 15
// baseline (speedup 1.0000x reference)
#include <cuda_runtime.h>
#include <cuda_fp16.h>
#include <math.h>
#include <stdint.h>

// ---------------------------------------------------------------------------
// Problem constants
// ---------------------------------------------------------------------------
constexpr int B_   = 8192;
constexpr int H_   = 768;
constexpr int H3_  = 2304;
constexpr int FF_  = 2048;
constexpr int MR_  = B_ * 12;

// ---------------------------------------------------------------------------
// Scratch. q-layout (no zero rows): g_gseqh, g_QKVh. Full layout: the rest.
// ---------------------------------------------------------------------------
__device__ __align__(256) __half g_gseqh[(size_t)MR_ * H_];
__device__ __align__(256) __half g_QKVh[(size_t)MR_ * H3_];
__device__ __align__(256) __half g_Ph  [(size_t)MR_ * H_];
__device__ __align__(256) __half g_Yh  [(size_t)MR_ * H_];
__device__ __align__(256) __half g_X1h [(size_t)MR_ * H_];
__device__ __align__(256) __half g_FFh [(size_t)MR_ * FF_];
__device__ __align__(256) __half g_zl  [(size_t)(2 * B_) * H_];
__device__ __align__(256) float  g_xdl [(size_t)(2 * B_) * H_];
__device__ int   g_len [B_];
__device__ int   g_off [B_];
__device__ int   g_qoff[B_];
__device__ int   g_rmap[MR_];
__device__ int   g_Mtot;
__device__ int   g_QMtot;
__device__ float g_bqkv[H3_];

constexpr size_t OFF_QKV = 0;
constexpr size_t OFF_WO  = OFF_QKV + (size_t)H_ * H3_;
constexpr size_t OFF_W1  = OFF_WO  + (size_t)H_ * H_;
constexpr size_t OFF_W2  = OFF_W1  + (size_t)H_ * FF_;
constexpr size_t OFF_WD  = OFF_W2  + (size_t)FF_ * H_;
constexpr size_t OFF_WL  = OFF_WD  + (size_t)H_ * H_;
__device__ __align__(256) __half g_Wh[OFF_WL + (size_t)H_ * H_];

// ---------------------------------------------------------------------------
// Helpers
// ---------------------------------------------------------------------------
__device__ __forceinline__ void cpasync16(uint32_t saddr, const void* g) {
    asm volatile("cp.async.cg.shared.global [%0], [%1], 16;\n" :: "r"(saddr), "l"(g));
}
__device__ __forceinline__ float warp_red(float v) {
#pragma unroll
    for (int o = 16; o > 0; o >>= 1) v += __shfl_xor_sync(0xffffffffu, v, o);
    return v;
}
__device__ __forceinline__ void ldsm4(uint32_t* r, uint32_t addr) {
    asm volatile("ldmatrix.sync.aligned.m8n8.x4.shared.b16 {%0,%1,%2,%3}, [%4];\n"
                 : "=r"(r[0]), "=r"(r[1]), "=r"(r[2]), "=r"(r[3]) : "r"(addr));
}
__device__ __forceinline__ void ldsm4t(uint32_t* r, uint32_t addr) {
    asm volatile("ldmatrix.sync.aligned.m8n8.x4.trans.shared.b16 {%0,%1,%2,%3}, [%4];\n"
                 : "=r"(r[0]), "=r"(r[1]), "=r"(r[2]), "=r"(r[3]) : "r"(addr));
}
__device__ __forceinline__ void mma16816(float* c, const uint32_t* a, uint32_t b0, uint32_t b1) {
    asm volatile(
        "mma.sync.aligned.m16n8k16.row.col.f32.f16.f16.f32 "
        "{%0,%1,%2,%3}, {%4,%5,%6,%7}, {%8,%9}, {%0,%1,%2,%3};\n"
        : "+f"(c[0]), "+f"(c[1]), "+f"(c[2]), "+f"(c[3])
        : "r"(a[0]), "r"(a[1]), "r"(a[2]), "r"(a[3]), "r"(b0), "r"(b1));
}

// ---------------------------------------------------------------------------
// Weight prep
// ---------------------------------------------------------------------------
constexpr int NHH = H_ * H_;
constexpr int NHF = H_ * FF_;
__global__ void pack_qkv(const float* __restrict__ Wq, const float* __restrict__ Wk,
                         const float* __restrict__ Wv, __half* __restrict__ dst) {
    int i = blockIdx.x * 256 + threadIdx.x;
    if (i >= NHH) return;
    int r = i / H_, c = i % H_;
    size_t o = (size_t)r * H3_ + c;
    dst[o]          = __float2half_rn(Wq[i]);
    dst[o + H_]     = __float2half_rn(Wk[i]);
    dst[o + 2 * H_] = __float2half_rn(Wv[i]);
}
__global__ void convh(const float* __restrict__ src, __half* __restrict__ dst, int n) {
    int i = blockIdx.x * 256 + threadIdx.x;
    if (i < n) dst[i] = __float2half_rn(src[i]);
}
__global__ void pack_bias(const float* __restrict__ bq, const float* __restrict__ bk,
                          const float* __restrict__ bv, float* __restrict__ dst) {
    int i = threadIdx.x + blockIdx.x * 256;
    if (i < H_) { dst[i] = bq[i]; dst[i + H_] = bk[i]; dst[i + 2 * H_] = bv[i]; }
}

// ---------------------------------------------------------------------------
// Fused len + dual exclusive scan (len & qlen packed in 64-bit)
// ---------------------------------------------------------------------------
__global__ void scan_kernel(const int* __restrict__ mask) {
    __shared__ long long sm[1024];
    const int t = threadIdx.x;
    int lens[8], qlens[8];
    long long loc[8];
    long long s = 0;
#pragma unroll
    for (int i = 0; i < 8; i++) {
        int b = t * 8 + i;
        int cnt = 0;
#pragma unroll
        for (int q = 0; q < 12; q++) cnt += (mask[b * 12 + q] != 0);
        int hlen = cnt < 11 ? cnt : 11;
        lens[i]  = hlen + 1;
        qlens[i] = (cnt >= 11) ? 12 : cnt;
        loc[i] = s;
        s += ((long long)lens[i] << 32) | (long long)qlens[i];
    }
    sm[t] = s;
    __syncthreads();
    for (int off = 1; off < 1024; off <<= 1) {
        long long v = (t >= off) ? sm[t - off] : 0;
        __syncthreads();
        sm[t] += v;
        __syncthreads();
    }
    const long long base = (t > 0) ? sm[t - 1] : 0;
#pragma unroll
    for (int i = 0; i < 8; i++) {
        long long p = base + loc[i];
        g_len [t * 8 + i] = lens[i];
        g_off [t * 8 + i] = (int)(p >> 32);
        g_qoff[t * 8 + i] = (int)(p & 0xffffffffLL);
    }
    if (t == 1023) {
        g_Mtot  = (int)(sm[1023] >> 32);
        g_QMtot = (int)(sm[1023] & 0xffffffffLL);
    }
}

// ---------------------------------------------------------------------------
// Gather: q-layout gseqh (no zero row) + rmap + z/lpool.
// ---------------------------------------------------------------------------
__global__ void gather_kernel(const float* __restrict__ z_k,
                              const float* __restrict__ buf,
                              const int*   __restrict__ mask,
                              const int*   __restrict__ bidx) {
    const int b = blockIdx.x;
    const int tid = threadIdx.x; // 192
    __shared__ int ord[12];
    __shared__ int s_nv;
    if (tid == 0) {
        int idx = bidx[b];
        int cnt = 0;
        for (int a = 11; a >= 0; a--) {
            int s = (idx - a + 24) % 12;
            if (mask[b * 12 + s]) ord[cnt++] = s;
        }
        s_nv = cnt;
    }
    __syncthreads();
    const int nv = s_nv;
    const int hlen = nv < 11 ? nv : 11;
    const int off  = g_off[b];
    const int qoff = g_qoff[b];
    const float4* zb4 = (const float4*)(z_k + (size_t)b * H_);

    for (int t = 0; t < hlen; t++) {
        __half2* dh = (__half2*)(g_gseqh + (size_t)(qoff + t) * H_);
        float4 v = ((const float4*)(buf + ((size_t)(b * 12 + ord[t])) * H_))[tid];
        dh[tid * 2]     = __floats2half2_rn(v.x, v.y);
        dh[tid * 2 + 1] = __floats2half2_rn(v.z, v.w);
    }
    if (hlen == 11) {
        __half2* dh = (__half2*)(g_gseqh + (size_t)(qoff + 11) * H_);
        float4 v = zb4[tid];
        dh[tid * 2]     = __floats2half2_rn(v.x, v.y);
        dh[tid * 2 + 1] = __floats2half2_rn(v.z, v.w);
    }
    if (tid == 0) {
        for (int t = 0; t < hlen; t++) g_rmap[off + t] = qoff + t;
        g_rmap[off + hlen] = (hlen == 11) ? (qoff + 11) : -1;
    }

    const int c4 = nv < 4 ? nv : 4;
    const float inv = 1.f / (float)(c4 + 1);
    {
        float4 zv = zb4[tid];
        float4 s = make_float4(0.f, 0.f, 0.f, 0.f);
        for (int t = 0; t < c4; t++) {
            float4 v = ((const float4*)(buf + ((size_t)(b * 12 + ord[t])) * H_))[tid];
            s.x += v.x; s.y += v.y; s.z += v.z; s.w += v.w;
        }
        if (c4 == 4) { s.x += zv.x; s.y += zv.y; s.z += zv.z; s.w += zv.w; }
        __half2* zh = (__half2*)(g_zl + (size_t)b * H_);
        __half2* lh = (__half2*)(g_zl + (size_t)(B_ + b) * H_);
        zh[tid * 2]     = __floats2half2_rn(zv.x, zv.y);
        zh[tid * 2 + 1] = __floats2half2_rn(zv.z, zv.w);
        lh[tid * 2]     = __floats2half2_rn(s.x * inv, s.y * inv);
        lh[tid * 2 + 1] = __floats2half2_rn(s.z * inv, s.w * inv);
    }
}

// ---------------------------------------------------------------------------
// fp16 tensor-core GEMM (128x128x64 tiles, 3-stage cp.async, 256 threads).
//   dynM: 0 all rows; 1 rows<g_Mtot; 2 rows<g_QMtot;
//         3 q-half1 (rows<g_qoff[B/2]); 4 q-half2; 5 full-half1; 6 full-half2.
//   rmap (epi 1): residual row index = rmap[r] (-1 -> zero).
//   epi: 1 half-resid -> half out, 2 relu->half, 3 tanh fp32, 4 half
// ---------------------------------------------------------------------------
#define NSTG 3
constexpr int A_STRIDE_B = 144;
constexpr int B_STRIDE_B = 272;
constexpr int A_BYTES = 128 * A_STRIDE_B;
constexpr int B_BYTES = 64 * B_STRIDE_B;
constexpr int STAGE   = A_BYTES + B_BYTES;   // 35840

__global__ void __launch_bounds__(256, 2)
gemm_f16(const __half* __restrict__ A, const __half* __restrict__ W,
         const __half* __restrict__ W2sel, const float* __restrict__ bias2, int rowSplit,
         const float* __restrict__ bias, const __half* __restrict__ residH,
         const int* __restrict__ rmap,
         void* __restrict__ Cout, int N, int K, int epi, int dynM)
{
    const int bn = blockIdx.x, bm = blockIdx.y;
    if (dynM) {
        int lo = 0, hi = 0x7fffffff;
        if (dynM == 1) hi = g_Mtot;
        else if (dynM == 2) hi = g_QMtot;
        else if (dynM == 3) hi = g_qoff[B_ / 2];
        else if (dynM == 4) { lo = g_qoff[B_ / 2]; hi = g_QMtot; }
        else if (dynM == 5) hi = g_off[B_ / 2];
        else if (dynM == 6) { lo = g_off[B_ / 2]; hi = g_Mtot; }
        if (bm * 128 >= hi || (bm + 1) * 128 <= lo) return;
    }

    extern __shared__ __align__(16) char smc[];
    const int tid = threadIdx.x, wid = tid >> 5, lane = tid & 31;
    const int wm = (wid & 1) * 64;
    const int wn = (wid >> 1) * 32;

    const uint32_t sbase = (uint32_t)__cvta_generic_to_shared(smc);
    const __half* Ab = A + (size_t)(bm * 128) * K;
    const bool useB2 = (W2sel != nullptr) && (bm * 128 >= rowSplit);
    const __half* Wuse = useB2 ? W2sel : W;
    const float*  buse = useB2 ? bias2 : bias;

    float acc[4][4][4];
#pragma unroll
    for (int mi = 0; mi < 4; mi++)
#pragma unroll
        for (int ni = 0; ni < 4; ni++)
#pragma unroll
            for (int r = 0; r < 4; r++) acc[mi][ni][r] = 0.f;

    auto load_stage = [&](int s, int kt) {
        uint32_t as = sbase + s * STAGE;
        uint32_t bs = as + A_BYTES;
        const __half* Ak = Ab + kt * 64;
        const __half* Wk = Wuse + (size_t)(kt * 64) * N + bn * 128;
#pragma unroll
        for (int i = 0; i < 4; i++) {
            int idx = tid + (i << 8);
            int r = idx >> 3, c = idx & 7;
            cpasync16(as + r * A_STRIDE_B + c * 16, Ak + (size_t)r * K + c * 8);
        }
#pragma unroll
        for (int i = 0; i < 4; i++) {
            int idx = tid + (i << 8);
            int r = idx >> 4, c = idx & 15;
            cpasync16(bs + r * B_STRIDE_B + c * 16, Wk + (size_t)r * N + c * 8);
        }
        asm volatile("cp.async.commit_group;\n" ::: "memory");
    };

    const int NIT = K >> 6;
    load_stage(0, 0);
    load_stage(1, 1);

    const int l15 = lane & 15;
    const int l16 = (lane >> 4) << 3;

    int s = 0, sl = 2;
    for (int it = 0; it < NIT; it++) {
        asm volatile("cp.async.wait_group %0;\n" :: "n"(NSTG - 2) : "memory");
        __syncthreads();
        if (it + 2 < NIT) {
            load_stage(sl, it + 2);
            if (++sl == NSTG) sl = 0;
        } else {
            asm volatile("cp.async.commit_group;\n" ::: "memory");
        }

        const uint32_t as = sbase + s * STAGE;
        const uint32_t bs = as + A_BYTES;
#pragma unroll
        for (int kh = 0; kh < 4; kh++) {
            const int kc = kh * 16;
            uint32_t a[4][4], b[2][4];
#pragma unroll
            for (int mi = 0; mi < 4; mi++)
                ldsm4(a[mi], as + (wm + mi * 16 + l15) * A_STRIDE_B + (kc + l16) * 2);
#pragma unroll
            for (int np = 0; np < 2; np++)
                ldsm4t(b[np], bs + (kc + l15) * B_STRIDE_B + (wn + np * 16 + l16) * 2);
#pragma unroll
            for (int mi = 0; mi < 4; mi++)
#pragma unroll
                for (int ni = 0; ni < 4; ni++)
                    mma16816(acc[mi][ni], a[mi],
                             b[ni >> 1][(ni & 1) * 2], b[ni >> 1][(ni & 1) * 2 + 1]);
        }
        if (++s == NSTG) s = 0;
    }

    const int g = lane >> 2, tg = lane & 3;
    const int row0 = bm * 128 + wm;
    const int col0 = bn * 128 + wn;
#pragma unroll
    for (int mi = 0; mi < 4; mi++) {
#pragma unroll
        for (int ni = 0; ni < 4; ni++) {
            const int c = col0 + ni * 8 + tg * 2;
            float2 bv = *(const float2*)(buse + c);
#pragma unroll
            for (int hh = 0; hh < 2; hh++) {
                const int r = row0 + mi * 16 + g + hh * 8;
                float v0 = acc[mi][ni][hh * 2]     + bv.x;
                float v1 = acc[mi][ni][hh * 2 + 1] + bv.y;
                const size_t off = (size_t)r * N + c;
                if (epi == 1) {
                    float2 rv = make_float2(0.f, 0.f);
                    if (rmap) {
                        int m = rmap[r];
                        if (m >= 0)
                            rv = __half22float2(*(const __half2*)(residH + (size_t)m * N + c));
                    } else {
                        rv = __half22float2(*(const __half2*)(residH + off));
                    }
                    v0 += rv.x; v1 += rv.y;
                    *(__half2*)((__half*)Cout + off) = __floats2half2_rn(v0, v1);
                } else if (epi == 2) {
                    v0 = fmaxf(v0, 0.f); v1 = fmaxf(v1, 0.f);
                    *(__half2*)((__half*)Cout + off) = __floats2half2_rn(v0, v1);
                } else if (epi == 3) {
                    *(float2*)((float*)Cout + off) = make_float2(tanhf(v0), tanhf(v1));
                } else {
                    *(__half2*)((__half*)Cout + off) = __floats2half2_rn(v0, v1);
                }
            }
        }
    }
}

// ---------------------------------------------------------------------------
// Attention on a batch range [b0, b0+gridDim.x): one CTA per batch.
// ---------------------------------------------------------------------------
constexpr int ATTN_SMEM = 12 * H3_ * 2 + 8 * 144 * 4;   // 59904

__global__ void __launch_bounds__(256, 3) attn_kernel(int b0) {
    extern __shared__ __align__(16) char asm_[];
    __half* qkv = (__half*)asm_;
    float*  sc  = (float*)(asm_ + 12 * H3_ * 2);

    const int b = b0 + blockIdx.x;
    const int tid = threadIdx.x;
    const int h = tid >> 5, lane = tid & 31;
    const int L = g_len[b];
    const int off  = g_off[b];
    const int qoff = g_qoff[b];
    const int qlen = (L == 12) ? 12 : L - 1;

    const int nchunk = qlen * (H3_ / 8);
    const uint4* gsrc = (const uint4*)(g_QKVh + (size_t)qoff * H3_);
    uint4* sdst = (uint4*)qkv;
    for (int i = tid; i < nchunk; i += 256) sdst[i] = gsrc[i];
    if (qlen < L) {
        __half* zrow = qkv + (size_t)(L - 1) * H3_;
        for (int i = tid; i < H3_; i += 256) zrow[i] = __float2half_rn(g_bqkv[i]);
    }
    __syncthreads();

    const __half* qh = qkv + h * 96;
    const __half* kh = qkv + h * 96 + H_;
    const __half* vh = qkv + h * 96 + 2 * H_;
    float* sch = sc + h * 144;

    for (int p = lane; p < L * L; p += 32) {
        int qi = p / L, ki = p % L;
        const __half2* qp = (const __half2*)(qh + qi * H3_);
        const __half2* kp = (const __half2*)(kh + ki * H3_);
        float s = 0.f;
#pragma unroll
        for (int d = 0; d < 48; d++) {
            float2 qf = __half22float2(qp[d]);
            float2 kf = __half22float2(kp[d]);
            s += qf.x * kf.x + qf.y * kf.y;
        }
        sch[qi * 12 + ki] = s * 0.10206207261596577f;
    }
    __syncwarp();

    if (lane < L) {
        float m = -3.0e38f;
        for (int j = 0; j < L; j++) m = fmaxf(m, sch[lane * 12 + j]);
        float sum = 0.f;
        for (int j = 0; j < L; j++) {
            float e = expf(sch[lane * 12 + j] - m);
            sch[lane * 12 + j] = e; sum += e;
        }
        float r = 1.f / sum;
        for (int j = 0; j < L; j++) sch[lane * 12 + j] *= r;
    }
    __syncwarp();

    for (int i = lane; i < L * 96; i += 32) {
        int qi = i / 96, d = i % 96;
        float o = 0.f;
        for (int j = 0; j < L; j++)
            o += sch[qi * 12 + j] * __half2float(vh[j * H3_ + d]);
        g_Ph[(size_t)(off + qi) * H_ + h * 96 + d] = __float2half_rn(o);
    }
}

// ---------------------------------------------------------------------------
// LayerNorm, warp-per-row (8 rows per 256-thread CTA, shuffle-only reduce).
// ---------------------------------------------------------------------------
__global__ void ln_kernel(const __half* __restrict__ X,
                          const float* __restrict__ gam,
                          const float* __restrict__ bet,
                          __half* __restrict__ Oh) {
    const int wid = threadIdx.x >> 5, lane = threadIdx.x & 31;
    const int row = blockIdx.x * 8 + wid;
    if (row >= g_Mtot) return;
    const __half2* x = (const __half2*)(X + (size_t)row * H_);
    float2 v[12];
    float s = 0.f, s2 = 0.f;
#pragma unroll
    for (int j = 0; j < 12; j++) {
        v[j] = __half22float2(x[lane + j * 32]);
        s  += v[j].x + v[j].y;
        s2 += v[j].x * v[j].x + v[j].y * v[j].y;
    }
    s  = warp_red(s);
    s2 = warp_red(s2);
    const float mu  = s * (1.f / 768.f);
    const float var = s2 * (1.f / 768.f) - mu * mu;
    const float inv = rsqrtf(var + 1e-5f);
    __half2* o = (__half2*)(Oh + (size_t)row * H_);
#pragma unroll
    for (int j = 0; j < 12; j++) {
        int c2 = lane + j * 32;
        float2 gg = *(const float2*)(gam + 2 * c2);
        float2 bb = *(const float2*)(bet + 2 * c2);
        o[c2] = __floats2half2_rn((v[j].x - mu) * inv * gg.x + bb.x,
                                  (v[j].y - mu) * inv * gg.y + bb.y);
    }
}

// ---------------------------------------------------------------------------
// Final: LN2 pool via warp-per-row (no block syncs in loop) + gate + mix.
// ---------------------------------------------------------------------------
__global__ void final_kernel(const __half* __restrict__ Y,
                             const float* __restrict__ ln2g,
                             const float* __restrict__ ln2b,
                             const float* __restrict__ Wg,
                             const float* __restrict__ bg,
                             float* __restrict__ out) {
    const int b = blockIdx.x, tid = threadIdx.x;
    const int wid = tid >> 5, lane = tid & 31;
    const int L = g_len[b];
    const int off = g_off[b];
    const float invL = 1.f / (float)L;

    __shared__ float sxg[768];
    for (int i = tid; i < 768; i += 256) sxg[i] = 0.f;
    __syncthreads();

    float2 gmv[12], btv[12];
#pragma unroll
    for (int j = 0; j < 12; j++) {
        int c2 = lane + j * 32;
        gmv[j] = *(const float2*)(ln2g + 2 * c2);
        btv[j] = *(const float2*)(ln2b + 2 * c2);
    }
    float2 xacc[12];
#pragma unroll
    for (int j = 0; j < 12; j++) xacc[j] = make_float2(0.f, 0.f);

    for (int t = wid; t < L; t += 8) {
        const __half2* x = (const __half2*)(Y + (size_t)(off + t) * H_);
        float2 v[12];
        float s = 0.f, s2 = 0.f;
#pragma unroll
        for (int j = 0; j < 12; j++) {
            v[j] = __half22float2(x[lane + j * 32]);
            s  += v[j].x + v[j].y;
            s2 += v[j].x * v[j].x + v[j].y * v[j].y;
        }
        s  = warp_red(s);
        s2 = warp_red(s2);
        const float mu  = s * (1.f / 768.f);
        const float var = s2 * (1.f / 768.f) - mu * mu;
        const float inv = rsqrtf(var + 1e-5f);
#pragma unroll
        for (int j = 0; j < 12; j++) {
            xacc[j].x += (v[j].x - mu) * inv * gmv[j].x + btv[j].x;
            xacc[j].y += (v[j].y - mu) * inv * gmv[j].y + btv[j].y;
        }
    }
    if (wid < L) {
#pragma unroll
        for (int j = 0; j < 12; j++) {
            int c2 = lane + j * 32;
            atomicAdd(&sxg[2 * c2],     xacc[j].x);
            atomicAdd(&sxg[2 * c2 + 1], xacc[j].y);
        }
    }
    __syncthreads();

    float xd[3], xl[3], xg[3];
    float p0 = 0.f, p1 = 0.f, p2 = 0.f;
#pragma unroll
    for (int i = 0; i < 3; i++) {
        int c = tid + i * 256;
        xd[i] = g_xdl[(size_t)b * H_ + c];
        xl[i] = g_xdl[(size_t)(B_ + b) * H_ + c];
        xg[i] = sxg[c] * invL;
        p0 += xd[i] * Wg[c * 3 + 0] + xl[i] * Wg[(768 + c) * 3 + 0] + xg[i] * Wg[(1536 + c) * 3 + 0];
        p1 += xd[i] * Wg[c * 3 + 1] + xl[i] * Wg[(768 + c) * 3 + 1] + xg[i] * Wg[(1536 + c) * 3 + 1];
        p2 += xd[i] * Wg[c * 3 + 2] + xl[i] * Wg[(768 + c) * 3 + 2] + xg[i] * Wg[(1536 + c) * 3 + 2];
    }
    p0 = warp_red(p0); p1 = warp_red(p1); p2 = warp_red(p2);
    __shared__ float red3[8][3];
    if ((tid & 31) == 0) { red3[tid >> 5][0] = p0; red3[tid >> 5][1] = p1; red3[tid >> 5][2] = p2; }
    __syncthreads();
    float l0 = bg[0], l1 = bg[1], l2 = bg[2];
#pragma unroll
    for (int w = 0; w < 8; w++) { l0 += red3[w][0]; l1 += red3[w][1]; l2 += red3[w][2]; }
    float m  = fmaxf(l0, fmaxf(l1, l2));
    float e0 = expf(l0 - m), e1 = expf(l1 - m), e2 = expf(l2 - m);
    float rs = 1.f / (e0 + e1 + e2);
    float g0 = e0 * rs, g1 = e1 * rs, g2 = e2 * rs;
#pragma unroll
    for (int i = 0; i < 3; i++) {
        int c = tid + i * 256;
        out[(size_t)b * H_ + c] = g0 * xd[i] + g1 * xl[i] + g2 * xg[i];
    }
}

// ---------------------------------------------------------------------------
// Launch — 3 streams: main chain, weight-prep/zl side, attention pipeline.
// ---------------------------------------------------------------------------
extern "C" void kernel_launch(void* const* d_in, const int* in_sizes, int n_in,
                              void* d_out, int out_size) {
    const float* z_k  = (const float*)d_in[0];
    const float* ctx  = (const float*)d_in[1];
    const int*   mask = (const int*)  d_in[2];
    const int*   bidx = (const int*)  d_in[3];
    const float* Wq = (const float*)d_in[4];  const float* bq = (const float*)d_in[5];
    const float* Wk = (const float*)d_in[6];  const float* bk = (const float*)d_in[7];
    const float* Wv = (const float*)d_in[8];  const float* bv = (const float*)d_in[9];
    const float* Wo = (const float*)d_in[10]; const float* bo = (const float*)d_in[11];
    const float* ln1g = (const float*)d_in[12]; const float* ln1b = (const float*)d_in[13];
    const float* W1 = (const float*)d_in[14]; const float* b1 = (const float*)d_in[15];
    const float* W2 = (const float*)d_in[16]; const float* b2 = (const float*)d_in[17];
    const float* ln2g = (const float*)d_in[18]; const float* ln2b = (const float*)d_in[19];
    const float* Wd = (const float*)d_in[20]; const float* bd = (const float*)d_in[21];
    const float* Wl = (const float*)d_in[22]; const float* bl = (const float*)d_in[23];
    const float* Wg = (const float*)d_in[24]; const float* bg = (const float*)d_in[25];
    float* out = (float*)d_out;

    static bool init_done = false;
    static cudaStream_t s2, s3;
    static cudaEvent_t evFork, evGather, evPack, evW, evJoin, evQ1, evQ2, evA1, evA2;
    const int dynSmem = NSTG * STAGE;   // 107520
    if (!init_done) {
        cudaFuncSetAttribute(gemm_f16, cudaFuncAttributeMaxDynamicSharedMemorySize, dynSmem);
        cudaFuncSetAttribute(attn_kernel, cudaFuncAttributeMaxDynamicSharedMemorySize, ATTN_SMEM);
        cudaStreamCreateWithFlags(&s2, cudaStreamNonBlocking);
        cudaStreamCreateWithFlags(&s3, cudaStreamNonBlocking);
        cudaEventCreateWithFlags(&evFork,   cudaEventDisableTiming);
        cudaEventCreateWithFlags(&evGather, cudaEventDisableTiming);
        cudaEventCreateWithFlags(&evPack,   cudaEventDisableTiming);
        cudaEventCreateWithFlags(&evW,      cudaEventDisableTiming);
        cudaEventCreateWithFlags(&evJoin,   cudaEventDisableTiming);
        cudaEventCreateWithFlags(&evQ1,     cudaEventDisableTiming);
        cudaEventCreateWithFlags(&evQ2,     cudaEventDisableTiming);
        cudaEventCreateWithFlags(&evA1,     cudaEventDisableTiming);
        cudaEventCreateWithFlags(&evA2,     cudaEventDisableTiming);
        init_done = true;
    }

    void *pgh, *pqkv, *pph, *pyh, *px1h, *pffh, *pzl, *pxdl, *pwh, *pbqkv, *prmap;
    cudaGetSymbolAddress(&pgh,  g_gseqh);
    cudaGetSymbolAddress(&pqkv, g_QKVh);   cudaGetSymbolAddress(&pph,  g_Ph);
    cudaGetSymbolAddress(&pyh,  g_Yh);     cudaGetSymbolAddress(&px1h, g_X1h);
    cudaGetSymbolAddress(&pffh, g_FFh);    cudaGetSymbolAddress(&pzl,  g_zl);
    cudaGetSymbolAddress(&pxdl, g_xdl);    cudaGetSymbolAddress(&pwh,  g_Wh);
    cudaGetSymbolAddress(&pbqkv, g_bqkv);  cudaGetSymbolAddress(&prmap, g_rmap);

    __half* fgh  = (__half*)pgh;
    __half* fqkv = (__half*)pqkv;  __half* fph  = (__half*)pph;
    __half* fyh  = (__half*)pyh;   __half* fx1h = (__half*)px1h;
    __half* fffh = (__half*)pffh;  __half* fzl  = (__half*)pzl;
    float*  fxdl = (float*)pxdl;   __half* fwh  = (__half*)pwh;
    float*  fbqkv = (float*)pbqkv; int*    frmap = (int*)prmap;

    // ---- fork -------------------------------------------------------------
    cudaEventRecord(evFork, 0);
    cudaStreamWaitEvent(s2, evFork, 0);

    // main: compaction + gather
    scan_kernel<<<1, 1024>>>(mask);
    gather_kernel<<<B_, 192>>>(z_k, ctx, mask, bidx);
    cudaEventRecord(evGather, 0);

    // side s2: QKV pack (gates QKV GEMM), remaining weight prep, zl GEMM
    pack_qkv<<<(NHH + 255) / 256, 256, 0, s2>>>(Wq, Wk, Wv, fwh + OFF_QKV);
    pack_bias<<<(H_ + 255) / 256, 256, 0, s2>>>(bq, bk, bv, fbqkv);
    cudaEventRecord(evPack, s2);
    convh<<<(NHH + 255) / 256, 256, 0, s2>>>(Wo, fwh + OFF_WO, NHH);
    convh<<<(NHF + 255) / 256, 256, 0, s2>>>(W1, fwh + OFF_W1, NHF);
    convh<<<(NHF + 255) / 256, 256, 0, s2>>>(W2, fwh + OFF_W2, NHF);
    convh<<<(NHH + 255) / 256, 256, 0, s2>>>(Wd, fwh + OFF_WD, NHH);
    convh<<<(NHH + 255) / 256, 256, 0, s2>>>(Wl, fwh + OFF_WL, NHH);
    cudaEventRecord(evW, s2);
    cudaStreamWaitEvent(s2, evGather, 0);
    gemm_f16<<<dim3(H_ / 128, (2 * B_) / 128), 256, dynSmem, s2>>>(
        fzl, fwh + OFF_WD, fwh + OFF_WL, bl, B_, bd, nullptr, nullptr,
        fxdl, H_, H_, 3, 0);
    cudaEventRecord(evJoin, s2);

    // main: QKV projection split into batch halves
    cudaStreamWaitEvent(0, evPack, 0);
    gemm_f16<<<dim3(H3_ / 128, MR_ / 128), 256, dynSmem>>>(
        fgh, fwh + OFF_QKV, nullptr, nullptr, 0, fbqkv, nullptr, nullptr,
        fqkv, H3_, H_, 4, 3);
    cudaEventRecord(evQ1, 0);
    gemm_f16<<<dim3(H3_ / 128, MR_ / 128), 256, dynSmem>>>(
        fgh, fwh + OFF_QKV, nullptr, nullptr, 0, fbqkv, nullptr, nullptr,
        fqkv, H3_, H_, 4, 4);
    cudaEventRecord(evQ2, 0);

    // s3: attention halves (attn1 overlaps QKV-half2; attn2 overlaps Wo-half1)
    cudaStreamWaitEvent(s3, evQ1, 0);
    attn_kernel<<<B_ / 2, 256, ATTN_SMEM, s3>>>(0);
    cudaEventRecord(evA1, s3);
    cudaStreamWaitEvent(s3, evQ2, 0);
    attn_kernel<<<B_ / 2, 256, ATTN_SMEM, s3>>>(B_ / 2);
    cudaEventRecord(evA2, s3);

    // main: Wo halves (+gseq residual via rmap)
    cudaStreamWaitEvent(0, evA1, 0);
    cudaStreamWaitEvent(0, evW, 0);
    gemm_f16<<<dim3(H_ / 128, MR_ / 128), 256, dynSmem>>>(
        fph, fwh + OFF_WO, nullptr, nullptr, 0, bo, fgh, frmap,
        fyh, H_, H_, 1, 5);
    cudaStreamWaitEvent(0, evA2, 0);
    gemm_f16<<<dim3(H_ / 128, MR_ / 128), 256, dynSmem>>>(
        fph, fwh + OFF_WO, nullptr, nullptr, 0, bo, fgh, frmap,
        fyh, H_, H_, 1, 6);

    // main: LN1, FFN
    ln_kernel<<<(MR_ + 7) / 8, 256>>>(fyh, ln1g, ln1b, fx1h);
    gemm_f16<<<dim3(FF_ / 128, MR_ / 128), 256, dynSmem>>>(
        fx1h, fwh + OFF_W1, nullptr, nullptr, 0, b1, nullptr, nullptr,
        fffh, FF_, H_, 2, 1);
    gemm_f16<<<dim3(H_ / 128, MR_ / 128), 256, dynSmem>>>(
        fffh, fwh + OFF_W2, nullptr, nullptr, 0, b2, fx1h, nullptr,
        fyh, H_, FF_, 1, 1);

    // join, then fused LN2 + pool + gate + output
    cudaStreamWaitEvent(0, evJoin, 0);
    final_kernel<<<B_, 256>>>(fyh, ln2g, ln2b, Wg, bg, out);
}

// round 16
// speedup vs baseline: 1.0127x; 1.0127x over previous
#include <cuda_runtime.h>
#include <cuda_fp16.h>
#include <math.h>
#include <stdint.h>

// ---------------------------------------------------------------------------
// Problem constants
// ---------------------------------------------------------------------------
constexpr int B_   = 8192;
constexpr int H_   = 768;
constexpr int H3_  = 2304;
constexpr int FF_  = 2048;
constexpr int MR_  = B_ * 12;

// ---------------------------------------------------------------------------
// Scratch. q-layout (no zero rows): g_gseqh, g_QKVh. Full layout: the rest.
// ---------------------------------------------------------------------------
__device__ __align__(256) __half g_gseqh[(size_t)MR_ * H_];
__device__ __align__(256) __half g_QKVh[(size_t)MR_ * H3_];
__device__ __align__(256) __half g_Ph  [(size_t)MR_ * H_];
__device__ __align__(256) __half g_Yh  [(size_t)MR_ * H_];
__device__ __align__(256) __half g_X1h [(size_t)MR_ * H_];
__device__ __align__(256) __half g_FFh [(size_t)MR_ * FF_];
__device__ __align__(256) __half g_zl  [(size_t)(2 * B_) * H_];
__device__ __align__(256) float  g_xdl [(size_t)(2 * B_) * H_];
__device__ int   g_len [B_];
__device__ int   g_off [B_];
__device__ int   g_qoff[B_];
__device__ int   g_rmap[MR_];
__device__ int   g_Mtot;
__device__ int   g_QMtot;
__device__ float g_bqkv[H3_];

constexpr size_t OFF_QKV = 0;
constexpr size_t OFF_WO  = OFF_QKV + (size_t)H_ * H3_;
constexpr size_t OFF_W1  = OFF_WO  + (size_t)H_ * H_;
constexpr size_t OFF_W2  = OFF_W1  + (size_t)H_ * FF_;
constexpr size_t OFF_WD  = OFF_W2  + (size_t)FF_ * H_;
constexpr size_t OFF_WL  = OFF_WD  + (size_t)H_ * H_;
__device__ __align__(256) __half g_Wh[OFF_WL + (size_t)H_ * H_];

// ---------------------------------------------------------------------------
// Helpers
// ---------------------------------------------------------------------------
__device__ __forceinline__ void cpasync16(uint32_t saddr, const void* g) {
    asm volatile("cp.async.cg.shared.global [%0], [%1], 16;\n" :: "r"(saddr), "l"(g));
}
__device__ __forceinline__ float warp_red(float v) {
#pragma unroll
    for (int o = 16; o > 0; o >>= 1) v += __shfl_xor_sync(0xffffffffu, v, o);
    return v;
}
__device__ __forceinline__ void ldsm4(uint32_t* r, uint32_t addr) {
    asm volatile("ldmatrix.sync.aligned.m8n8.x4.shared.b16 {%0,%1,%2,%3}, [%4];\n"
                 : "=r"(r[0]), "=r"(r[1]), "=r"(r[2]), "=r"(r[3]) : "r"(addr));
}
__device__ __forceinline__ void ldsm4t(uint32_t* r, uint32_t addr) {
    asm volatile("ldmatrix.sync.aligned.m8n8.x4.trans.shared.b16 {%0,%1,%2,%3}, [%4];\n"
                 : "=r"(r[0]), "=r"(r[1]), "=r"(r[2]), "=r"(r[3]) : "r"(addr));
}
__device__ __forceinline__ void mma16816(float* c, const uint32_t* a, uint32_t b0, uint32_t b1) {
    asm volatile(
        "mma.sync.aligned.m16n8k16.row.col.f32.f16.f16.f32 "
        "{%0,%1,%2,%3}, {%4,%5,%6,%7}, {%8,%9}, {%0,%1,%2,%3};\n"
        : "+f"(c[0]), "+f"(c[1]), "+f"(c[2]), "+f"(c[3])
        : "r"(a[0]), "r"(a[1]), "r"(a[2]), "r"(a[3]), "r"(b0), "r"(b1));
}

// ---------------------------------------------------------------------------
// Weight prep
// ---------------------------------------------------------------------------
constexpr int NHH = H_ * H_;
constexpr int NHF = H_ * FF_;
__global__ void pack_qkv(const float* __restrict__ Wq, const float* __restrict__ Wk,
                         const float* __restrict__ Wv, __half* __restrict__ dst) {
    int i = blockIdx.x * 256 + threadIdx.x;
    if (i >= NHH) return;
    int r = i / H_, c = i % H_;
    size_t o = (size_t)r * H3_ + c;
    dst[o]          = __float2half_rn(Wq[i]);
    dst[o + H_]     = __float2half_rn(Wk[i]);
    dst[o + 2 * H_] = __float2half_rn(Wv[i]);
}
__global__ void convh(const float* __restrict__ src, __half* __restrict__ dst, int n) {
    int i = blockIdx.x * 256 + threadIdx.x;
    if (i < n) dst[i] = __float2half_rn(src[i]);
}
__global__ void pack_bias(const float* __restrict__ bq, const float* __restrict__ bk,
                          const float* __restrict__ bv, float* __restrict__ dst) {
    int i = threadIdx.x + blockIdx.x * 256;
    if (i < H_) { dst[i] = bq[i]; dst[i + H_] = bk[i]; dst[i + 2 * H_] = bv[i]; }
}

// ---------------------------------------------------------------------------
// Fused len + dual exclusive scan (len & qlen packed in 64-bit)
// ---------------------------------------------------------------------------
__global__ void scan_kernel(const int* __restrict__ mask) {
    __shared__ long long sm[1024];
    const int t = threadIdx.x;
    int lens[8], qlens[8];
    long long loc[8];
    long long s = 0;
#pragma unroll
    for (int i = 0; i < 8; i++) {
        int b = t * 8 + i;
        int cnt = 0;
#pragma unroll
        for (int q = 0; q < 12; q++) cnt += (mask[b * 12 + q] != 0);
        int hlen = cnt < 11 ? cnt : 11;
        lens[i]  = hlen + 1;
        qlens[i] = (cnt >= 11) ? 12 : cnt;
        loc[i] = s;
        s += ((long long)lens[i] << 32) | (long long)qlens[i];
    }
    sm[t] = s;
    __syncthreads();
    for (int off = 1; off < 1024; off <<= 1) {
        long long v = (t >= off) ? sm[t - off] : 0;
        __syncthreads();
        sm[t] += v;
        __syncthreads();
    }
    const long long base = (t > 0) ? sm[t - 1] : 0;
#pragma unroll
    for (int i = 0; i < 8; i++) {
        long long p = base + loc[i];
        g_len [t * 8 + i] = lens[i];
        g_off [t * 8 + i] = (int)(p >> 32);
        g_qoff[t * 8 + i] = (int)(p & 0xffffffffLL);
    }
    if (t == 1023) {
        g_Mtot  = (int)(sm[1023] >> 32);
        g_QMtot = (int)(sm[1023] & 0xffffffffLL);
    }
}

// ---------------------------------------------------------------------------
// Gather: q-layout gseqh (no zero row) + rmap + z/lpool.
// ---------------------------------------------------------------------------
__global__ void gather_kernel(const float* __restrict__ z_k,
                              const float* __restrict__ buf,
                              const int*   __restrict__ mask,
                              const int*   __restrict__ bidx) {
    const int b = blockIdx.x;
    const int tid = threadIdx.x; // 192
    __shared__ int ord[12];
    __shared__ int s_nv;
    if (tid == 0) {
        int idx = bidx[b];
        int cnt = 0;
        for (int a = 11; a >= 0; a--) {
            int s = (idx - a + 24) % 12;
            if (mask[b * 12 + s]) ord[cnt++] = s;
        }
        s_nv = cnt;
    }
    __syncthreads();
    const int nv = s_nv;
    const int hlen = nv < 11 ? nv : 11;
    const int off  = g_off[b];
    const int qoff = g_qoff[b];
    const float4* zb4 = (const float4*)(z_k + (size_t)b * H_);

    for (int t = 0; t < hlen; t++) {
        __half2* dh = (__half2*)(g_gseqh + (size_t)(qoff + t) * H_);
        float4 v = ((const float4*)(buf + ((size_t)(b * 12 + ord[t])) * H_))[tid];
        dh[tid * 2]     = __floats2half2_rn(v.x, v.y);
        dh[tid * 2 + 1] = __floats2half2_rn(v.z, v.w);
    }
    if (hlen == 11) {
        __half2* dh = (__half2*)(g_gseqh + (size_t)(qoff + 11) * H_);
        float4 v = zb4[tid];
        dh[tid * 2]     = __floats2half2_rn(v.x, v.y);
        dh[tid * 2 + 1] = __floats2half2_rn(v.z, v.w);
    }
    if (tid == 0) {
        for (int t = 0; t < hlen; t++) g_rmap[off + t] = qoff + t;
        g_rmap[off + hlen] = (hlen == 11) ? (qoff + 11) : -1;
    }

    const int c4 = nv < 4 ? nv : 4;
    const float inv = 1.f / (float)(c4 + 1);
    {
        float4 zv = zb4[tid];
        float4 s = make_float4(0.f, 0.f, 0.f, 0.f);
        for (int t = 0; t < c4; t++) {
            float4 v = ((const float4*)(buf + ((size_t)(b * 12 + ord[t])) * H_))[tid];
            s.x += v.x; s.y += v.y; s.z += v.z; s.w += v.w;
        }
        if (c4 == 4) { s.x += zv.x; s.y += zv.y; s.z += zv.z; s.w += zv.w; }
        __half2* zh = (__half2*)(g_zl + (size_t)b * H_);
        __half2* lh = (__half2*)(g_zl + (size_t)(B_ + b) * H_);
        zh[tid * 2]     = __floats2half2_rn(zv.x, zv.y);
        zh[tid * 2 + 1] = __floats2half2_rn(zv.z, zv.w);
        lh[tid * 2]     = __floats2half2_rn(s.x * inv, s.y * inv);
        lh[tid * 2 + 1] = __floats2half2_rn(s.z * inv, s.w * inv);
    }
}

// ---------------------------------------------------------------------------
// fp16 tensor-core GEMM (128x128x64 tiles, 3-stage cp.async, 256 threads).
//   dynM: 0 all rows; 1 rows<g_Mtot; 2 rows<g_QMtot.
//   rmap (epi 1): residual row index = rmap[r] (-1 -> zero).
//   epi: 1 half-resid -> half out, 2 relu->half, 3 tanh fp32, 4 half
// ---------------------------------------------------------------------------
#define NSTG 3
constexpr int A_STRIDE_B = 144;
constexpr int B_STRIDE_B = 272;
constexpr int A_BYTES = 128 * A_STRIDE_B;
constexpr int B_BYTES = 64 * B_STRIDE_B;
constexpr int STAGE   = A_BYTES + B_BYTES;   // 35840

__global__ void __launch_bounds__(256, 2)
gemm_f16(const __half* __restrict__ A, const __half* __restrict__ W,
         const __half* __restrict__ W2sel, const float* __restrict__ bias2, int rowSplit,
         const float* __restrict__ bias, const __half* __restrict__ residH,
         const int* __restrict__ rmap,
         void* __restrict__ Cout, int N, int K, int epi, int dynM)
{
    const int bn = blockIdx.x, bm = blockIdx.y;
    if (dynM) {
        const int lim = (dynM == 2) ? g_QMtot : g_Mtot;
        if (bm * 128 >= lim) return;
    }

    extern __shared__ __align__(16) char smc[];
    const int tid = threadIdx.x, wid = tid >> 5, lane = tid & 31;
    const int wm = (wid & 1) * 64;
    const int wn = (wid >> 1) * 32;

    const uint32_t sbase = (uint32_t)__cvta_generic_to_shared(smc);
    const __half* Ab = A + (size_t)(bm * 128) * K;
    const bool useB2 = (W2sel != nullptr) && (bm * 128 >= rowSplit);
    const __half* Wuse = useB2 ? W2sel : W;
    const float*  buse = useB2 ? bias2 : bias;

    float acc[4][4][4];
#pragma unroll
    for (int mi = 0; mi < 4; mi++)
#pragma unroll
        for (int ni = 0; ni < 4; ni++)
#pragma unroll
            for (int r = 0; r < 4; r++) acc[mi][ni][r] = 0.f;

    auto load_stage = [&](int s, int kt) {
        uint32_t as = sbase + s * STAGE;
        uint32_t bs = as + A_BYTES;
        const __half* Ak = Ab + kt * 64;
        const __half* Wk = Wuse + (size_t)(kt * 64) * N + bn * 128;
#pragma unroll
        for (int i = 0; i < 4; i++) {
            int idx = tid + (i << 8);
            int r = idx >> 3, c = idx & 7;
            cpasync16(as + r * A_STRIDE_B + c * 16, Ak + (size_t)r * K + c * 8);
        }
#pragma unroll
        for (int i = 0; i < 4; i++) {
            int idx = tid + (i << 8);
            int r = idx >> 4, c = idx & 15;
            cpasync16(bs + r * B_STRIDE_B + c * 16, Wk + (size_t)r * N + c * 8);
        }
        asm volatile("cp.async.commit_group;\n" ::: "memory");
    };

    const int NIT = K >> 6;
    load_stage(0, 0);
    load_stage(1, 1);

    const int l15 = lane & 15;
    const int l16 = (lane >> 4) << 3;

    int s = 0, sl = 2;
    for (int it = 0; it < NIT; it++) {
        asm volatile("cp.async.wait_group %0;\n" :: "n"(NSTG - 2) : "memory");
        __syncthreads();
        if (it + 2 < NIT) {
            load_stage(sl, it + 2);
            if (++sl == NSTG) sl = 0;
        } else {
            asm volatile("cp.async.commit_group;\n" ::: "memory");
        }

        const uint32_t as = sbase + s * STAGE;
        const uint32_t bs = as + A_BYTES;
#pragma unroll
        for (int kh = 0; kh < 4; kh++) {
            const int kc = kh * 16;
            uint32_t a[4][4], b[2][4];
#pragma unroll
            for (int mi = 0; mi < 4; mi++)
                ldsm4(a[mi], as + (wm + mi * 16 + l15) * A_STRIDE_B + (kc + l16) * 2);
#pragma unroll
            for (int np = 0; np < 2; np++)
                ldsm4t(b[np], bs + (kc + l15) * B_STRIDE_B + (wn + np * 16 + l16) * 2);
#pragma unroll
            for (int mi = 0; mi < 4; mi++)
#pragma unroll
                for (int ni = 0; ni < 4; ni++)
                    mma16816(acc[mi][ni], a[mi],
                             b[ni >> 1][(ni & 1) * 2], b[ni >> 1][(ni & 1) * 2 + 1]);
        }
        if (++s == NSTG) s = 0;
    }

    const int g = lane >> 2, tg = lane & 3;
    const int row0 = bm * 128 + wm;
    const int col0 = bn * 128 + wn;
#pragma unroll
    for (int mi = 0; mi < 4; mi++) {
#pragma unroll
        for (int ni = 0; ni < 4; ni++) {
            const int c = col0 + ni * 8 + tg * 2;
            float2 bv = *(const float2*)(buse + c);
#pragma unroll
            for (int hh = 0; hh < 2; hh++) {
                const int r = row0 + mi * 16 + g + hh * 8;
                float v0 = acc[mi][ni][hh * 2]     + bv.x;
                float v1 = acc[mi][ni][hh * 2 + 1] + bv.y;
                const size_t off = (size_t)r * N + c;
                if (epi == 1) {
                    float2 rv = make_float2(0.f, 0.f);
                    if (rmap) {
                        int m = rmap[r];
                        if (m >= 0)
                            rv = __half22float2(*(const __half2*)(residH + (size_t)m * N + c));
                    } else {
                        rv = __half22float2(*(const __half2*)(residH + off));
                    }
                    v0 += rv.x; v1 += rv.y;
                    *(__half2*)((__half*)Cout + off) = __floats2half2_rn(v0, v1);
                } else if (epi == 2) {
                    v0 = fmaxf(v0, 0.f); v1 = fmaxf(v1, 0.f);
                    *(__half2*)((__half*)Cout + off) = __floats2half2_rn(v0, v1);
                } else if (epi == 3) {
                    *(float2*)((float*)Cout + off) = make_float2(tanhf(v0), tanhf(v1));
                } else {
                    *(__half2*)((__half*)Cout + off) = __floats2half2_rn(v0, v1);
                }
            }
        }
    }
}

// ---------------------------------------------------------------------------
// Attention: one CTA per batch. Synthesizes the zero row from g_bqkv.
// ---------------------------------------------------------------------------
constexpr int ATTN_SMEM = 12 * H3_ * 2 + 8 * 144 * 4;   // 59904

__global__ void __launch_bounds__(256, 3) attn_kernel() {
    extern __shared__ __align__(16) char asm_[];
    __half* qkv = (__half*)asm_;
    float*  sc  = (float*)(asm_ + 12 * H3_ * 2);

    const int b = blockIdx.x;
    const int tid = threadIdx.x;
    const int h = tid >> 5, lane = tid & 31;
    const int L = g_len[b];
    const int off  = g_off[b];
    const int qoff = g_qoff[b];
    const int qlen = (L == 12) ? 12 : L - 1;

    const int nchunk = qlen * (H3_ / 8);
    const uint4* gsrc = (const uint4*)(g_QKVh + (size_t)qoff * H3_);
    uint4* sdst = (uint4*)qkv;
    for (int i = tid; i < nchunk; i += 256) sdst[i] = gsrc[i];
    if (qlen < L) {
        __half* zrow = qkv + (size_t)(L - 1) * H3_;
        for (int i = tid; i < H3_; i += 256) zrow[i] = __float2half_rn(g_bqkv[i]);
    }
    __syncthreads();

    const __half* qh = qkv + h * 96;
    const __half* kh = qkv + h * 96 + H_;
    const __half* vh = qkv + h * 96 + 2 * H_;
    float* sch = sc + h * 144;

    for (int p = lane; p < L * L; p += 32) {
        int qi = p / L, ki = p % L;
        const __half2* qp = (const __half2*)(qh + qi * H3_);
        const __half2* kp = (const __half2*)(kh + ki * H3_);
        float s = 0.f;
#pragma unroll
        for (int d = 0; d < 48; d++) {
            float2 qf = __half22float2(qp[d]);
            float2 kf = __half22float2(kp[d]);
            s += qf.x * kf.x + qf.y * kf.y;
        }
        sch[qi * 12 + ki] = s * 0.10206207261596577f;
    }
    __syncwarp();

    if (lane < L) {
        float m = -3.0e38f;
        for (int j = 0; j < L; j++) m = fmaxf(m, sch[lane * 12 + j]);
        float sum = 0.f;
        for (int j = 0; j < L; j++) {
            float e = expf(sch[lane * 12 + j] - m);
            sch[lane * 12 + j] = e; sum += e;
        }
        float r = 1.f / sum;
        for (int j = 0; j < L; j++) sch[lane * 12 + j] *= r;
    }
    __syncwarp();

    for (int i = lane; i < L * 96; i += 32) {
        int qi = i / 96, d = i % 96;
        float o = 0.f;
        for (int j = 0; j < L; j++)
            o += sch[qi * 12 + j] * __half2float(vh[j * H3_ + d]);
        g_Ph[(size_t)(off + qi) * H_ + h * 96 + d] = __float2half_rn(o);
    }
}

// ---------------------------------------------------------------------------
// LayerNorm, warp-per-row (8 rows per 256-thread CTA, shuffle-only reduce).
// ---------------------------------------------------------------------------
__global__ void ln_kernel(const __half* __restrict__ X,
                          const float* __restrict__ gam,
                          const float* __restrict__ bet,
                          __half* __restrict__ Oh) {
    const int wid = threadIdx.x >> 5, lane = threadIdx.x & 31;
    const int row = blockIdx.x * 8 + wid;
    if (row >= g_Mtot) return;
    const __half2* x = (const __half2*)(X + (size_t)row * H_);
    float2 v[12];
    float s = 0.f, s2 = 0.f;
#pragma unroll
    for (int j = 0; j < 12; j++) {
        v[j] = __half22float2(x[lane + j * 32]);
        s  += v[j].x + v[j].y;
        s2 += v[j].x * v[j].x + v[j].y * v[j].y;
    }
    s  = warp_red(s);
    s2 = warp_red(s2);
    const float mu  = s * (1.f / 768.f);
    const float var = s2 * (1.f / 768.f) - mu * mu;
    const float inv = rsqrtf(var + 1e-5f);
    __half2* o = (__half2*)(Oh + (size_t)row * H_);
#pragma unroll
    for (int j = 0; j < 12; j++) {
        int c2 = lane + j * 32;
        float2 gg = *(const float2*)(gam + 2 * c2);
        float2 bb = *(const float2*)(bet + 2 * c2);
        o[c2] = __floats2half2_rn((v[j].x - mu) * inv * gg.x + bb.x,
                                  (v[j].y - mu) * inv * gg.y + bb.y);
    }
}

// ---------------------------------------------------------------------------
// Final: LN2 pool via warp-per-row (no block syncs in loop) + gate + mix.
// ---------------------------------------------------------------------------
__global__ void final_kernel(const __half* __restrict__ Y,
                             const float* __restrict__ ln2g,
                             const float* __restrict__ ln2b,
                             const float* __restrict__ Wg,
                             const float* __restrict__ bg,
                             float* __restrict__ out) {
    const int b = blockIdx.x, tid = threadIdx.x;
    const int wid = tid >> 5, lane = tid & 31;
    const int L = g_len[b];
    const int off = g_off[b];
    const float invL = 1.f / (float)L;

    __shared__ float sxg[768];
    for (int i = tid; i < 768; i += 256) sxg[i] = 0.f;
    __syncthreads();

    float2 gmv[12], btv[12];
#pragma unroll
    for (int j = 0; j < 12; j++) {
        int c2 = lane + j * 32;
        gmv[j] = *(const float2*)(ln2g + 2 * c2);
        btv[j] = *(const float2*)(ln2b + 2 * c2);
    }
    float2 xacc[12];
#pragma unroll
    for (int j = 0; j < 12; j++) xacc[j] = make_float2(0.f, 0.f);

    for (int t = wid; t < L; t += 8) {
        const __half2* x = (const __half2*)(Y + (size_t)(off + t) * H_);
        float2 v[12];
        float s = 0.f, s2 = 0.f;
#pragma unroll
        for (int j = 0; j < 12; j++) {
            v[j] = __half22float2(x[lane + j * 32]);
            s  += v[j].x + v[j].y;
            s2 += v[j].x * v[j].x + v[j].y * v[j].y;
        }
        s  = warp_red(s);
        s2 = warp_red(s2);
        const float mu  = s * (1.f / 768.f);
        const float var = s2 * (1.f / 768.f) - mu * mu;
        const float inv = rsqrtf(var + 1e-5f);
#pragma unroll
        for (int j = 0; j < 12; j++) {
            xacc[j].x += (v[j].x - mu) * inv * gmv[j].x + btv[j].x;
            xacc[j].y += (v[j].y - mu) * inv * gmv[j].y + btv[j].y;
        }
    }
    if (wid < L) {
#pragma unroll
        for (int j = 0; j < 12; j++) {
            int c2 = lane + j * 32;
            atomicAdd(&sxg[2 * c2],     xacc[j].x);
            atomicAdd(&sxg[2 * c2 + 1], xacc[j].y);
        }
    }
    __syncthreads();

    float xd[3], xl[3], xg[3];
    float p0 = 0.f, p1 = 0.f, p2 = 0.f;
#pragma unroll
    for (int i = 0; i < 3; i++) {
        int c = tid + i * 256;
        xd[i] = g_xdl[(size_t)b * H_ + c];
        xl[i] = g_xdl[(size_t)(B_ + b) * H_ + c];
        xg[i] = sxg[c] * invL;
        p0 += xd[i] * Wg[c * 3 + 0] + xl[i] * Wg[(768 + c) * 3 + 0] + xg[i] * Wg[(1536 + c) * 3 + 0];
        p1 += xd[i] * Wg[c * 3 + 1] + xl[i] * Wg[(768 + c) * 3 + 1] + xg[i] * Wg[(1536 + c) * 3 + 1];
        p2 += xd[i] * Wg[c * 3 + 2] + xl[i] * Wg[(768 + c) * 3 + 2] + xg[i] * Wg[(1536 + c) * 3 + 2];
    }
    p0 = warp_red(p0); p1 = warp_red(p1); p2 = warp_red(p2);
    __shared__ float red3[8][3];
    if ((tid & 31) == 0) { red3[tid >> 5][0] = p0; red3[tid >> 5][1] = p1; red3[tid >> 5][2] = p2; }
    __syncthreads();
    float l0 = bg[0], l1 = bg[1], l2 = bg[2];
#pragma unroll
    for (int w = 0; w < 8; w++) { l0 += red3[w][0]; l1 += red3[w][1]; l2 += red3[w][2]; }
    float m  = fmaxf(l0, fmaxf(l1, l2));
    float e0 = expf(l0 - m), e1 = expf(l1 - m), e2 = expf(l2 - m);
    float rs = 1.f / (e0 + e1 + e2);
    float g0 = e0 * rs, g1 = e1 * rs, g2 = e2 * rs;
#pragma unroll
    for (int i = 0; i < 3; i++) {
        int c = tid + i * 256;
        out[(size_t)b * H_ + c] = g0 * xd[i] + g1 * xl[i] + g2 * xg[i];
    }
}

// ---------------------------------------------------------------------------
// Launch — R14 structure: main chain + one side stream (weights + zl GEMM).
// ---------------------------------------------------------------------------
extern "C" void kernel_launch(void* const* d_in, const int* in_sizes, int n_in,
                              void* d_out, int out_size) {
    const float* z_k  = (const float*)d_in[0];
    const float* ctx  = (const float*)d_in[1];
    const int*   mask = (const int*)  d_in[2];
    const int*   bidx = (const int*)  d_in[3];
    const float* Wq = (const float*)d_in[4];  const float* bq = (const float*)d_in[5];
    const float* Wk = (const float*)d_in[6];  const float* bk = (const float*)d_in[7];
    const float* Wv = (const float*)d_in[8];  const float* bv = (const float*)d_in[9];
    const float* Wo = (const float*)d_in[10]; const float* bo = (const float*)d_in[11];
    const float* ln1g = (const float*)d_in[12]; const float* ln1b = (const float*)d_in[13];
    const float* W1 = (const float*)d_in[14]; const float* b1 = (const float*)d_in[15];
    const float* W2 = (const float*)d_in[16]; const float* b2 = (const float*)d_in[17];
    const float* ln2g = (const float*)d_in[18]; const float* ln2b = (const float*)d_in[19];
    const float* Wd = (const float*)d_in[20]; const float* bd = (const float*)d_in[21];
    const float* Wl = (const float*)d_in[22]; const float* bl = (const float*)d_in[23];
    const float* Wg = (const float*)d_in[24]; const float* bg = (const float*)d_in[25];
    float* out = (float*)d_out;

    static bool init_done = false;
    static cudaStream_t s2;
    static cudaEvent_t evFork, evGather, evPack, evW, evJoin;
    const int dynSmem = NSTG * STAGE;   // 107520
    if (!init_done) {
        cudaFuncSetAttribute(gemm_f16, cudaFuncAttributeMaxDynamicSharedMemorySize, dynSmem);
        cudaFuncSetAttribute(attn_kernel, cudaFuncAttributeMaxDynamicSharedMemorySize, ATTN_SMEM);
        cudaStreamCreateWithFlags(&s2, cudaStreamNonBlocking);
        cudaEventCreateWithFlags(&evFork,   cudaEventDisableTiming);
        cudaEventCreateWithFlags(&evGather, cudaEventDisableTiming);
        cudaEventCreateWithFlags(&evPack,   cudaEventDisableTiming);
        cudaEventCreateWithFlags(&evW,      cudaEventDisableTiming);
        cudaEventCreateWithFlags(&evJoin,   cudaEventDisableTiming);
        init_done = true;
    }

    void *pgh, *pqkv, *pph, *pyh, *px1h, *pffh, *pzl, *pxdl, *pwh, *pbqkv, *prmap;
    cudaGetSymbolAddress(&pgh,  g_gseqh);
    cudaGetSymbolAddress(&pqkv, g_QKVh);   cudaGetSymbolAddress(&pph,  g_Ph);
    cudaGetSymbolAddress(&pyh,  g_Yh);     cudaGetSymbolAddress(&px1h, g_X1h);
    cudaGetSymbolAddress(&pffh, g_FFh);    cudaGetSymbolAddress(&pzl,  g_zl);
    cudaGetSymbolAddress(&pxdl, g_xdl);    cudaGetSymbolAddress(&pwh,  g_Wh);
    cudaGetSymbolAddress(&pbqkv, g_bqkv);  cudaGetSymbolAddress(&prmap, g_rmap);

    __half* fgh  = (__half*)pgh;
    __half* fqkv = (__half*)pqkv;  __half* fph  = (__half*)pph;
    __half* fyh  = (__half*)pyh;   __half* fx1h = (__half*)px1h;
    __half* fffh = (__half*)pffh;  __half* fzl  = (__half*)pzl;
    float*  fxdl = (float*)pxdl;   __half* fwh  = (__half*)pwh;
    float*  fbqkv = (float*)pbqkv; int*    frmap = (int*)prmap;

    // ---- fork -------------------------------------------------------------
    cudaEventRecord(evFork, 0);
    cudaStreamWaitEvent(s2, evFork, 0);

    // main: compaction + gather
    scan_kernel<<<1, 1024>>>(mask);
    gather_kernel<<<B_, 192>>>(z_k, ctx, mask, bidx);
    cudaEventRecord(evGather, 0);

    // side s2: QKV pack first (gates QKV GEMM), then remaining weight prep
    pack_qkv<<<(NHH + 255) / 256, 256, 0, s2>>>(Wq, Wk, Wv, fwh + OFF_QKV);
    pack_bias<<<(H_ + 255) / 256, 256, 0, s2>>>(bq, bk, bv, fbqkv);
    cudaEventRecord(evPack, s2);
    convh<<<(NHH + 255) / 256, 256, 0, s2>>>(Wo, fwh + OFF_WO, NHH);
    convh<<<(NHF + 255) / 256, 256, 0, s2>>>(W1, fwh + OFF_W1, NHF);
    convh<<<(NHF + 255) / 256, 256, 0, s2>>>(W2, fwh + OFF_W2, NHF);
    convh<<<(NHH + 255) / 256, 256, 0, s2>>>(Wd, fwh + OFF_WD, NHH);
    convh<<<(NHH + 255) / 256, 256, 0, s2>>>(Wl, fwh + OFF_WL, NHH);
    cudaEventRecord(evW, s2);
    // side: stacked z/lpool GEMM (needs gather)
    cudaStreamWaitEvent(s2, evGather, 0);
    gemm_f16<<<dim3(H_ / 128, (2 * B_) / 128), 256, dynSmem, s2>>>(
        fzl, fwh + OFF_WD, fwh + OFF_WL, bl, B_, bd, nullptr, nullptr,
        fxdl, H_, H_, 3, 0);
    cudaEventRecord(evJoin, s2);

    // main: QKV projection (q-compact rows) + attention
    cudaStreamWaitEvent(0, evPack, 0);
    gemm_f16<<<dim3(H3_ / 128, MR_ / 128), 256, dynSmem>>>(
        fgh, fwh + OFF_QKV, nullptr, nullptr, 0, fbqkv, nullptr, nullptr,
        fqkv, H3_, H_, 4, 2);
    attn_kernel<<<B_, 256, ATTN_SMEM>>>();

    // main: Wo projection (+gseq residual via rmap, half out), LN1
    cudaStreamWaitEvent(0, evW, 0);
    gemm_f16<<<dim3(H_ / 128, MR_ / 128), 256, dynSmem>>>(
        fph, fwh + OFF_WO, nullptr, nullptr, 0, bo, fgh, frmap,
        fyh, H_, H_, 1, 1);
    ln_kernel<<<(MR_ + 7) / 8, 256>>>(fyh, ln1g, ln1b, fx1h);

    // main: FFN
    gemm_f16<<<dim3(FF_ / 128, MR_ / 128), 256, dynSmem>>>(
        fx1h, fwh + OFF_W1, nullptr, nullptr, 0, b1, nullptr, nullptr,
        fffh, FF_, H_, 2, 1);
    gemm_f16<<<dim3(H_ / 128, MR_ / 128), 256, dynSmem>>>(
        fffh, fwh + OFF_W2, nullptr, nullptr, 0, b2, fx1h, nullptr,
        fyh, H_, FF_, 1, 1);

    // join, then fused LN2 + pool + gate + output
    cudaStreamWaitEvent(0, evJoin, 0);
    final_kernel<<<B_, 256>>>(fyh, ln2g, ln2b, Wg, bg, out);
}

// round 17
// speedup vs baseline: 1.0145x; 1.0018x over previous
#include <cuda_runtime.h>
#include <cuda_fp16.h>
#include <math.h>
#include <stdint.h>

// ---------------------------------------------------------------------------
// Problem constants
// ---------------------------------------------------------------------------
constexpr int B_   = 8192;
constexpr int H_   = 768;
constexpr int H3_  = 2304;
constexpr int FF_  = 2048;
constexpr int MR_  = B_ * 12;

// ---------------------------------------------------------------------------
// Scratch. q-layout (no zero rows): g_gseqh, g_QKVh. Full layout: the rest.
// ---------------------------------------------------------------------------
__device__ __align__(256) __half g_gseqh[(size_t)MR_ * H_];
__device__ __align__(256) __half g_QKVh[(size_t)MR_ * H3_];
__device__ __align__(256) __half g_Ph  [(size_t)MR_ * H_];
__device__ __align__(256) __half g_Yh  [(size_t)MR_ * H_];
__device__ __align__(256) __half g_X1h [(size_t)MR_ * H_];
__device__ __align__(256) __half g_FFh [(size_t)MR_ * FF_];
__device__ __align__(256) __half g_zl  [(size_t)(2 * B_) * H_];
__device__ __align__(256) float  g_xdl [(size_t)(2 * B_) * H_];
__device__ int   g_len [B_];
__device__ int   g_off [B_];
__device__ int   g_qoff[B_];
__device__ int   g_rmap[MR_];
__device__ int   g_Mtot;
__device__ int   g_QMtot;
__device__ float g_bqkv[H3_];

constexpr size_t OFF_QKV = 0;
constexpr size_t OFF_WO  = OFF_QKV + (size_t)H_ * H3_;
constexpr size_t OFF_W1  = OFF_WO  + (size_t)H_ * H_;
constexpr size_t OFF_W2  = OFF_W1  + (size_t)H_ * FF_;
constexpr size_t OFF_WD  = OFF_W2  + (size_t)FF_ * H_;
constexpr size_t OFF_WL  = OFF_WD  + (size_t)H_ * H_;
__device__ __align__(256) __half g_Wh[OFF_WL + (size_t)H_ * H_];

// ---------------------------------------------------------------------------
// Helpers
// ---------------------------------------------------------------------------
__device__ __forceinline__ void cpasync16(uint32_t saddr, const void* g) {
    asm volatile("cp.async.cg.shared.global [%0], [%1], 16;\n" :: "r"(saddr), "l"(g));
}
__device__ __forceinline__ float warp_red(float v) {
#pragma unroll
    for (int o = 16; o > 0; o >>= 1) v += __shfl_xor_sync(0xffffffffu, v, o);
    return v;
}
__device__ __forceinline__ void ldsm4(uint32_t* r, uint32_t addr) {
    asm volatile("ldmatrix.sync.aligned.m8n8.x4.shared.b16 {%0,%1,%2,%3}, [%4];\n"
                 : "=r"(r[0]), "=r"(r[1]), "=r"(r[2]), "=r"(r[3]) : "r"(addr));
}
__device__ __forceinline__ void ldsm4t(uint32_t* r, uint32_t addr) {
    asm volatile("ldmatrix.sync.aligned.m8n8.x4.trans.shared.b16 {%0,%1,%2,%3}, [%4];\n"
                 : "=r"(r[0]), "=r"(r[1]), "=r"(r[2]), "=r"(r[3]) : "r"(addr));
}
__device__ __forceinline__ void mma16816(float* c, const uint32_t* a, uint32_t b0, uint32_t b1) {
    asm volatile(
        "mma.sync.aligned.m16n8k16.row.col.f32.f16.f16.f32 "
        "{%0,%1,%2,%3}, {%4,%5,%6,%7}, {%8,%9}, {%0,%1,%2,%3};\n"
        : "+f"(c[0]), "+f"(c[1]), "+f"(c[2]), "+f"(c[3])
        : "r"(a[0]), "r"(a[1]), "r"(a[2]), "r"(a[3]), "r"(b0), "r"(b1));
}

// ---------------------------------------------------------------------------
// Weight prep
// ---------------------------------------------------------------------------
constexpr int NHH = H_ * H_;
constexpr int NHF = H_ * FF_;
__global__ void pack_qkv(const float* __restrict__ Wq, const float* __restrict__ Wk,
                         const float* __restrict__ Wv, __half* __restrict__ dst) {
    int i = blockIdx.x * 256 + threadIdx.x;
    if (i >= NHH) return;
    int r = i / H_, c = i % H_;
    size_t o = (size_t)r * H3_ + c;
    dst[o]          = __float2half_rn(Wq[i]);
    dst[o + H_]     = __float2half_rn(Wk[i]);
    dst[o + 2 * H_] = __float2half_rn(Wv[i]);
}
__global__ void convh(const float* __restrict__ src, __half* __restrict__ dst, int n) {
    int i = blockIdx.x * 256 + threadIdx.x;
    if (i < n) dst[i] = __float2half_rn(src[i]);
}
__global__ void pack_bias(const float* __restrict__ bq, const float* __restrict__ bk,
                          const float* __restrict__ bv, float* __restrict__ dst) {
    int i = threadIdx.x + blockIdx.x * 256;
    if (i < H_) { dst[i] = bq[i]; dst[i + H_] = bk[i]; dst[i + 2 * H_] = bv[i]; }
}

// ---------------------------------------------------------------------------
// Fused len + dual exclusive scan (len & qlen packed in 64-bit)
// ---------------------------------------------------------------------------
__global__ void scan_kernel(const int* __restrict__ mask) {
    __shared__ long long sm[1024];
    const int t = threadIdx.x;
    int lens[8], qlens[8];
    long long loc[8];
    long long s = 0;
#pragma unroll
    for (int i = 0; i < 8; i++) {
        int b = t * 8 + i;
        int cnt = 0;
#pragma unroll
        for (int q = 0; q < 12; q++) cnt += (mask[b * 12 + q] != 0);
        int hlen = cnt < 11 ? cnt : 11;
        lens[i]  = hlen + 1;
        qlens[i] = (cnt >= 11) ? 12 : cnt;
        loc[i] = s;
        s += ((long long)lens[i] << 32) | (long long)qlens[i];
    }
    sm[t] = s;
    __syncthreads();
    for (int off = 1; off < 1024; off <<= 1) {
        long long v = (t >= off) ? sm[t - off] : 0;
        __syncthreads();
        sm[t] += v;
        __syncthreads();
    }
    const long long base = (t > 0) ? sm[t - 1] : 0;
#pragma unroll
    for (int i = 0; i < 8; i++) {
        long long p = base + loc[i];
        g_len [t * 8 + i] = lens[i];
        g_off [t * 8 + i] = (int)(p >> 32);
        g_qoff[t * 8 + i] = (int)(p & 0xffffffffLL);
    }
    if (t == 1023) {
        g_Mtot  = (int)(sm[1023] >> 32);
        g_QMtot = (int)(sm[1023] & 0xffffffffLL);
    }
}

// ---------------------------------------------------------------------------
// Gather: q-layout gseqh (no zero row) + rmap + z/lpool.
// ---------------------------------------------------------------------------
__global__ void gather_kernel(const float* __restrict__ z_k,
                              const float* __restrict__ buf,
                              const int*   __restrict__ mask,
                              const int*   __restrict__ bidx) {
    const int b = blockIdx.x;
    const int tid = threadIdx.x; // 192
    __shared__ int ord[12];
    __shared__ int s_nv;
    if (tid == 0) {
        int idx = bidx[b];
        int cnt = 0;
        for (int a = 11; a >= 0; a--) {
            int s = (idx - a + 24) % 12;
            if (mask[b * 12 + s]) ord[cnt++] = s;
        }
        s_nv = cnt;
    }
    __syncthreads();
    const int nv = s_nv;
    const int hlen = nv < 11 ? nv : 11;
    const int off  = g_off[b];
    const int qoff = g_qoff[b];
    const float4* zb4 = (const float4*)(z_k + (size_t)b * H_);

    for (int t = 0; t < hlen; t++) {
        __half2* dh = (__half2*)(g_gseqh + (size_t)(qoff + t) * H_);
        float4 v = ((const float4*)(buf + ((size_t)(b * 12 + ord[t])) * H_))[tid];
        dh[tid * 2]     = __floats2half2_rn(v.x, v.y);
        dh[tid * 2 + 1] = __floats2half2_rn(v.z, v.w);
    }
    if (hlen == 11) {
        __half2* dh = (__half2*)(g_gseqh + (size_t)(qoff + 11) * H_);
        float4 v = zb4[tid];
        dh[tid * 2]     = __floats2half2_rn(v.x, v.y);
        dh[tid * 2 + 1] = __floats2half2_rn(v.z, v.w);
    }
    if (tid == 0) {
        for (int t = 0; t < hlen; t++) g_rmap[off + t] = qoff + t;
        g_rmap[off + hlen] = (hlen == 11) ? (qoff + 11) : -1;
    }

    const int c4 = nv < 4 ? nv : 4;
    const float inv = 1.f / (float)(c4 + 1);
    {
        float4 zv = zb4[tid];
        float4 s = make_float4(0.f, 0.f, 0.f, 0.f);
        for (int t = 0; t < c4; t++) {
            float4 v = ((const float4*)(buf + ((size_t)(b * 12 + ord[t])) * H_))[tid];
            s.x += v.x; s.y += v.y; s.z += v.z; s.w += v.w;
        }
        if (c4 == 4) { s.x += zv.x; s.y += zv.y; s.z += zv.z; s.w += zv.w; }
        __half2* zh = (__half2*)(g_zl + (size_t)b * H_);
        __half2* lh = (__half2*)(g_zl + (size_t)(B_ + b) * H_);
        zh[tid * 2]     = __floats2half2_rn(zv.x, zv.y);
        zh[tid * 2 + 1] = __floats2half2_rn(zv.z, zv.w);
        lh[tid * 2]     = __floats2half2_rn(s.x * inv, s.y * inv);
        lh[tid * 2 + 1] = __floats2half2_rn(s.z * inv, s.w * inv);
    }
}

// ---------------------------------------------------------------------------
// fp16 tensor-core GEMM (128x128x64 tiles, 3-stage cp.async, 256 threads).
//   dynM: 0 all rows; 1 rows<g_Mtot; 2 rows<g_QMtot.
//   rmap (epi 1): residual row index = rmap[r] (-1 -> zero).
//   epi: 1 half-resid -> half out, 2 relu->half, 3 tanh fp32, 4 half
// ---------------------------------------------------------------------------
#define NSTG 3
constexpr int A_STRIDE_B = 144;
constexpr int B_STRIDE_B = 272;
constexpr int A_BYTES = 128 * A_STRIDE_B;
constexpr int B_BYTES = 64 * B_STRIDE_B;
constexpr int STAGE   = A_BYTES + B_BYTES;   // 35840

__global__ void __launch_bounds__(256, 2)
gemm_f16(const __half* __restrict__ A, const __half* __restrict__ W,
         const __half* __restrict__ W2sel, const float* __restrict__ bias2, int rowSplit,
         const float* __restrict__ bias, const __half* __restrict__ residH,
         const int* __restrict__ rmap,
         void* __restrict__ Cout, int N, int K, int epi, int dynM)
{
    const int bn = blockIdx.x, bm = blockIdx.y;
    if (dynM) {
        const int lim = (dynM == 2) ? g_QMtot : g_Mtot;
        if (bm * 128 >= lim) return;
    }

    extern __shared__ __align__(16) char smc[];
    const int tid = threadIdx.x, wid = tid >> 5, lane = tid & 31;
    const int wm = (wid & 1) * 64;
    const int wn = (wid >> 1) * 32;

    const uint32_t sbase = (uint32_t)__cvta_generic_to_shared(smc);
    const __half* Ab = A + (size_t)(bm * 128) * K;
    const bool useB2 = (W2sel != nullptr) && (bm * 128 >= rowSplit);
    const __half* Wuse = useB2 ? W2sel : W;
    const float*  buse = useB2 ? bias2 : bias;

    float acc[4][4][4];
#pragma unroll
    for (int mi = 0; mi < 4; mi++)
#pragma unroll
        for (int ni = 0; ni < 4; ni++)
#pragma unroll
            for (int r = 0; r < 4; r++) acc[mi][ni][r] = 0.f;

    auto load_stage = [&](int s, int kt) {
        uint32_t as = sbase + s * STAGE;
        uint32_t bs = as + A_BYTES;
        const __half* Ak = Ab + kt * 64;
        const __half* Wk = Wuse + (size_t)(kt * 64) * N + bn * 128;
#pragma unroll
        for (int i = 0; i < 4; i++) {
            int idx = tid + (i << 8);
            int r = idx >> 3, c = idx & 7;
            cpasync16(as + r * A_STRIDE_B + c * 16, Ak + (size_t)r * K + c * 8);
        }
#pragma unroll
        for (int i = 0; i < 4; i++) {
            int idx = tid + (i << 8);
            int r = idx >> 4, c = idx & 15;
            cpasync16(bs + r * B_STRIDE_B + c * 16, Wk + (size_t)r * N + c * 8);
        }
        asm volatile("cp.async.commit_group;\n" ::: "memory");
    };

    const int NIT = K >> 6;
    load_stage(0, 0);
    load_stage(1, 1);

    const int l15 = lane & 15;
    const int l16 = (lane >> 4) << 3;

    int s = 0, sl = 2;
    for (int it = 0; it < NIT; it++) {
        asm volatile("cp.async.wait_group %0;\n" :: "n"(NSTG - 2) : "memory");
        __syncthreads();
        if (it + 2 < NIT) {
            load_stage(sl, it + 2);
            if (++sl == NSTG) sl = 0;
        } else {
            asm volatile("cp.async.commit_group;\n" ::: "memory");
        }

        const uint32_t as = sbase + s * STAGE;
        const uint32_t bs = as + A_BYTES;
#pragma unroll
        for (int kh = 0; kh < 4; kh++) {
            const int kc = kh * 16;
            uint32_t a[4][4], b[2][4];
#pragma unroll
            for (int mi = 0; mi < 4; mi++)
                ldsm4(a[mi], as + (wm + mi * 16 + l15) * A_STRIDE_B + (kc + l16) * 2);
#pragma unroll
            for (int np = 0; np < 2; np++)
                ldsm4t(b[np], bs + (kc + l15) * B_STRIDE_B + (wn + np * 16 + l16) * 2);
#pragma unroll
            for (int mi = 0; mi < 4; mi++)
#pragma unroll
                for (int ni = 0; ni < 4; ni++)
                    mma16816(acc[mi][ni], a[mi],
                             b[ni >> 1][(ni & 1) * 2], b[ni >> 1][(ni & 1) * 2 + 1]);
        }
        if (++s == NSTG) s = 0;
    }

    const int g = lane >> 2, tg = lane & 3;
    const int row0 = bm * 128 + wm;
    const int col0 = bn * 128 + wn;
#pragma unroll
    for (int mi = 0; mi < 4; mi++) {
#pragma unroll
        for (int ni = 0; ni < 4; ni++) {
            const int c = col0 + ni * 8 + tg * 2;
            float2 bv = *(const float2*)(buse + c);
#pragma unroll
            for (int hh = 0; hh < 2; hh++) {
                const int r = row0 + mi * 16 + g + hh * 8;
                float v0 = acc[mi][ni][hh * 2]     + bv.x;
                float v1 = acc[mi][ni][hh * 2 + 1] + bv.y;
                const size_t off = (size_t)r * N + c;
                if (epi == 1) {
                    float2 rv = make_float2(0.f, 0.f);
                    if (rmap) {
                        int m = rmap[r];
                        if (m >= 0)
                            rv = __half22float2(*(const __half2*)(residH + (size_t)m * N + c));
                    } else {
                        rv = __half22float2(*(const __half2*)(residH + off));
                    }
                    v0 += rv.x; v1 += rv.y;
                    *(__half2*)((__half*)Cout + off) = __floats2half2_rn(v0, v1);
                } else if (epi == 2) {
                    v0 = fmaxf(v0, 0.f); v1 = fmaxf(v1, 0.f);
                    *(__half2*)((__half*)Cout + off) = __floats2half2_rn(v0, v1);
                } else if (epi == 3) {
                    *(float2*)((float*)Cout + off) = make_float2(tanhf(v0), tanhf(v1));
                } else {
                    *(__half2*)((__half*)Cout + off) = __floats2half2_rn(v0, v1);
                }
            }
        }
    }
}

// ---------------------------------------------------------------------------
// Attention: one CTA per batch. Synthesizes the zero row from g_bqkv.
// ---------------------------------------------------------------------------
constexpr int ATTN_SMEM = 12 * H3_ * 2 + 8 * 144 * 4;   // 59904

__global__ void __launch_bounds__(256, 3) attn_kernel() {
    extern __shared__ __align__(16) char asm_[];
    __half* qkv = (__half*)asm_;
    float*  sc  = (float*)(asm_ + 12 * H3_ * 2);

    const int b = blockIdx.x;
    const int tid = threadIdx.x;
    const int h = tid >> 5, lane = tid & 31;
    const int L = g_len[b];
    const int off  = g_off[b];
    const int qoff = g_qoff[b];
    const int qlen = (L == 12) ? 12 : L - 1;

    const int nchunk = qlen * (H3_ / 8);
    const uint4* gsrc = (const uint4*)(g_QKVh + (size_t)qoff * H3_);
    uint4* sdst = (uint4*)qkv;
    for (int i = tid; i < nchunk; i += 256) sdst[i] = gsrc[i];
    if (qlen < L) {
        __half* zrow = qkv + (size_t)(L - 1) * H3_;
        for (int i = tid; i < H3_; i += 256) zrow[i] = __float2half_rn(g_bqkv[i]);
    }
    __syncthreads();

    const __half* qh = qkv + h * 96;
    const __half* kh = qkv + h * 96 + H_;
    const __half* vh = qkv + h * 96 + 2 * H_;
    float* sch = sc + h * 144;

    for (int p = lane; p < L * L; p += 32) {
        int qi = p / L, ki = p % L;
        const __half2* qp = (const __half2*)(qh + qi * H3_);
        const __half2* kp = (const __half2*)(kh + ki * H3_);
        float s = 0.f;
#pragma unroll
        for (int d = 0; d < 48; d++) {
            float2 qf = __half22float2(qp[d]);
            float2 kf = __half22float2(kp[d]);
            s += qf.x * kf.x + qf.y * kf.y;
        }
        sch[qi * 12 + ki] = s * 0.10206207261596577f;
    }
    __syncwarp();

    if (lane < L) {
        float m = -3.0e38f;
        for (int j = 0; j < L; j++) m = fmaxf(m, sch[lane * 12 + j]);
        float sum = 0.f;
        for (int j = 0; j < L; j++) {
            float e = expf(sch[lane * 12 + j] - m);
            sch[lane * 12 + j] = e; sum += e;
        }
        float r = 1.f / sum;
        for (int j = 0; j < L; j++) sch[lane * 12 + j] *= r;
    }
    __syncwarp();

    for (int i = lane; i < L * 96; i += 32) {
        int qi = i / 96, d = i % 96;
        float o = 0.f;
        for (int j = 0; j < L; j++)
            o += sch[qi * 12 + j] * __half2float(vh[j * H3_ + d]);
        g_Ph[(size_t)(off + qi) * H_ + h * 96 + d] = __float2half_rn(o);
    }
}

// ---------------------------------------------------------------------------
// LayerNorm, warp-per-row (8 rows per 256-thread CTA, shuffle-only reduce).
// ---------------------------------------------------------------------------
__global__ void ln_kernel(const __half* __restrict__ X,
                          const float* __restrict__ gam,
                          const float* __restrict__ bet,
                          __half* __restrict__ Oh) {
    const int wid = threadIdx.x >> 5, lane = threadIdx.x & 31;
    const int row = blockIdx.x * 8 + wid;
    if (row >= g_Mtot) return;
    const __half2* x = (const __half2*)(X + (size_t)row * H_);
    float2 v[12];
    float s = 0.f, s2 = 0.f;
#pragma unroll
    for (int j = 0; j < 12; j++) {
        v[j] = __half22float2(x[lane + j * 32]);
        s  += v[j].x + v[j].y;
        s2 += v[j].x * v[j].x + v[j].y * v[j].y;
    }
    s  = warp_red(s);
    s2 = warp_red(s2);
    const float mu  = s * (1.f / 768.f);
    const float var = s2 * (1.f / 768.f) - mu * mu;
    const float inv = rsqrtf(var + 1e-5f);
    __half2* o = (__half2*)(Oh + (size_t)row * H_);
#pragma unroll
    for (int j = 0; j < 12; j++) {
        int c2 = lane + j * 32;
        float2 gg = *(const float2*)(gam + 2 * c2);
        float2 bb = *(const float2*)(bet + 2 * c2);
        o[c2] = __floats2half2_rn((v[j].x - mu) * inv * gg.x + bb.x,
                                  (v[j].y - mu) * inv * gg.y + bb.y);
    }
}

// ---------------------------------------------------------------------------
// Final: LN2 pool via warp-per-row (no block syncs in loop) + gate + mix.
// ---------------------------------------------------------------------------
__global__ void final_kernel(const __half* __restrict__ Y,
                             const float* __restrict__ ln2g,
                             const float* __restrict__ ln2b,
                             const float* __restrict__ Wg,
                             const float* __restrict__ bg,
                             float* __restrict__ out) {
    const int b = blockIdx.x, tid = threadIdx.x;
    const int wid = tid >> 5, lane = tid & 31;
    const int L = g_len[b];
    const int off = g_off[b];
    const float invL = 1.f / (float)L;

    __shared__ float sxg[768];
    for (int i = tid; i < 768; i += 256) sxg[i] = 0.f;
    __syncthreads();

    float2 gmv[12], btv[12];
#pragma unroll
    for (int j = 0; j < 12; j++) {
        int c2 = lane + j * 32;
        gmv[j] = *(const float2*)(ln2g + 2 * c2);
        btv[j] = *(const float2*)(ln2b + 2 * c2);
    }
    float2 xacc[12];
#pragma unroll
    for (int j = 0; j < 12; j++) xacc[j] = make_float2(0.f, 0.f);

    for (int t = wid; t < L; t += 8) {
        const __half2* x = (const __half2*)(Y + (size_t)(off + t) * H_);
        float2 v[12];
        float s = 0.f, s2 = 0.f;
#pragma unroll
        for (int j = 0; j < 12; j++) {
            v[j] = __half22float2(x[lane + j * 32]);
            s  += v[j].x + v[j].y;
            s2 += v[j].x * v[j].x + v[j].y * v[j].y;
        }
        s  = warp_red(s);
        s2 = warp_red(s2);
        const float mu  = s * (1.f / 768.f);
        const float var = s2 * (1.f / 768.f) - mu * mu;
        const float inv = rsqrtf(var + 1e-5f);
#pragma unroll
        for (int j = 0; j < 12; j++) {
            xacc[j].x += (v[j].x - mu) * inv * gmv[j].x + btv[j].x;
            xacc[j].y += (v[j].y - mu) * inv * gmv[j].y + btv[j].y;
        }
    }
    if (wid < L) {
#pragma unroll
        for (int j = 0; j < 12; j++) {
            int c2 = lane + j * 32;
            atomicAdd(&sxg[2 * c2],     xacc[j].x);
            atomicAdd(&sxg[2 * c2 + 1], xacc[j].y);
        }
    }
    __syncthreads();

    float xd[3], xl[3], xg[3];
    float p0 = 0.f, p1 = 0.f, p2 = 0.f;
#pragma unroll
    for (int i = 0; i < 3; i++) {
        int c = tid + i * 256;
        xd[i] = g_xdl[(size_t)b * H_ + c];
        xl[i] = g_xdl[(size_t)(B_ + b) * H_ + c];
        xg[i] = sxg[c] * invL;
        p0 += xd[i] * Wg[c * 3 + 0] + xl[i] * Wg[(768 + c) * 3 + 0] + xg[i] * Wg[(1536 + c) * 3 + 0];
        p1 += xd[i] * Wg[c * 3 + 1] + xl[i] * Wg[(768 + c) * 3 + 1] + xg[i] * Wg[(1536 + c) * 3 + 1];
        p2 += xd[i] * Wg[c * 3 + 2] + xl[i] * Wg[(768 + c) * 3 + 2] + xg[i] * Wg[(1536 + c) * 3 + 2];
    }
    p0 = warp_red(p0); p1 = warp_red(p1); p2 = warp_red(p2);
    __shared__ float red3[8][3];
    if ((tid & 31) == 0) { red3[tid >> 5][0] = p0; red3[tid >> 5][1] = p1; red3[tid >> 5][2] = p2; }
    __syncthreads();
    float l0 = bg[0], l1 = bg[1], l2 = bg[2];
#pragma unroll
    for (int w = 0; w < 8; w++) { l0 += red3[w][0]; l1 += red3[w][1]; l2 += red3[w][2]; }
    float m  = fmaxf(l0, fmaxf(l1, l2));
    float e0 = expf(l0 - m), e1 = expf(l1 - m), e2 = expf(l2 - m);
    float rs = 1.f / (e0 + e1 + e2);
    float g0 = e0 * rs, g1 = e1 * rs, g2 = e2 * rs;
#pragma unroll
    for (int i = 0; i < 3; i++) {
        int c = tid + i * 256;
        out[(size_t)b * H_ + c] = g0 * xd[i] + g1 * xl[i] + g2 * xg[i];
    }
}

// ---------------------------------------------------------------------------
// Launch — R14 structure: main chain + one side stream (weights + zl GEMM).
// ---------------------------------------------------------------------------
extern "C" void kernel_launch(void* const* d_in, const int* in_sizes, int n_in,
                              void* d_out, int out_size) {
    const float* z_k  = (const float*)d_in[0];
    const float* ctx  = (const float*)d_in[1];
    const int*   mask = (const int*)  d_in[2];
    const int*   bidx = (const int*)  d_in[3];
    const float* Wq = (const float*)d_in[4];  const float* bq = (const float*)d_in[5];
    const float* Wk = (const float*)d_in[6];  const float* bk = (const float*)d_in[7];
    const float* Wv = (const float*)d_in[8];  const float* bv = (const float*)d_in[9];
    const float* Wo = (const float*)d_in[10]; const float* bo = (const float*)d_in[11];
    const float* ln1g = (const float*)d_in[12]; const float* ln1b = (const float*)d_in[13];
    const float* W1 = (const float*)d_in[14]; const float* b1 = (const float*)d_in[15];
    const float* W2 = (const float*)d_in[16]; const float* b2 = (const float*)d_in[17];
    const float* ln2g = (const float*)d_in[18]; const float* ln2b = (const float*)d_in[19];
    const float* Wd = (const float*)d_in[20]; const float* bd = (const float*)d_in[21];
    const float* Wl = (const float*)d_in[22]; const float* bl = (const float*)d_in[23];
    const float* Wg = (const float*)d_in[24]; const float* bg = (const float*)d_in[25];
    float* out = (float*)d_out;

    static bool init_done = false;
    static cudaStream_t s2;
    static cudaEvent_t evFork, evGather, evPack, evW, evJoin;
    const int dynSmem = NSTG * STAGE;   // 107520
    if (!init_done) {
        cudaFuncSetAttribute(gemm_f16, cudaFuncAttributeMaxDynamicSharedMemorySize, dynSmem);
        cudaFuncSetAttribute(attn_kernel, cudaFuncAttributeMaxDynamicSharedMemorySize, ATTN_SMEM);
        cudaStreamCreateWithFlags(&s2, cudaStreamNonBlocking);
        cudaEventCreateWithFlags(&evFork,   cudaEventDisableTiming);
        cudaEventCreateWithFlags(&evGather, cudaEventDisableTiming);
        cudaEventCreateWithFlags(&evPack,   cudaEventDisableTiming);
        cudaEventCreateWithFlags(&evW,      cudaEventDisableTiming);
        cudaEventCreateWithFlags(&evJoin,   cudaEventDisableTiming);
        init_done = true;
    }

    void *pgh, *pqkv, *pph, *pyh, *px1h, *pffh, *pzl, *pxdl, *pwh, *pbqkv, *prmap;
    cudaGetSymbolAddress(&pgh,  g_gseqh);
    cudaGetSymbolAddress(&pqkv, g_QKVh);   cudaGetSymbolAddress(&pph,  g_Ph);
    cudaGetSymbolAddress(&pyh,  g_Yh);     cudaGetSymbolAddress(&px1h, g_X1h);
    cudaGetSymbolAddress(&pffh, g_FFh);    cudaGetSymbolAddress(&pzl,  g_zl);
    cudaGetSymbolAddress(&pxdl, g_xdl);    cudaGetSymbolAddress(&pwh,  g_Wh);
    cudaGetSymbolAddress(&pbqkv, g_bqkv);  cudaGetSymbolAddress(&prmap, g_rmap);

    __half* fgh  = (__half*)pgh;
    __half* fqkv = (__half*)pqkv;  __half* fph  = (__half*)pph;
    __half* fyh  = (__half*)pyh;   __half* fx1h = (__half*)px1h;
    __half* fffh = (__half*)pffh;  __half* fzl  = (__half*)pzl;
    float*  fxdl = (float*)pxdl;   __half* fwh  = (__half*)pwh;
    float*  fbqkv = (float*)pbqkv; int*    frmap = (int*)prmap;

    // ---- fork -------------------------------------------------------------
    cudaEventRecord(evFork, 0);
    cudaStreamWaitEvent(s2, evFork, 0);

    // main: compaction + gather
    scan_kernel<<<1, 1024>>>(mask);
    gather_kernel<<<B_, 192>>>(z_k, ctx, mask, bidx);
    cudaEventRecord(evGather, 0);

    // side s2: QKV pack first (gates QKV GEMM), then remaining weight prep
    pack_qkv<<<(NHH + 255) / 256, 256, 0, s2>>>(Wq, Wk, Wv, fwh + OFF_QKV);
    pack_bias<<<(H_ + 255) / 256, 256, 0, s2>>>(bq, bk, bv, fbqkv);
    cudaEventRecord(evPack, s2);
    convh<<<(NHH + 255) / 256, 256, 0, s2>>>(Wo, fwh + OFF_WO, NHH);
    convh<<<(NHF + 255) / 256, 256, 0, s2>>>(W1, fwh + OFF_W1, NHF);
    convh<<<(NHF + 255) / 256, 256, 0, s2>>>(W2, fwh + OFF_W2, NHF);
    convh<<<(NHH + 255) / 256, 256, 0, s2>>>(Wd, fwh + OFF_WD, NHH);
    convh<<<(NHH + 255) / 256, 256, 0, s2>>>(Wl, fwh + OFF_WL, NHH);
    cudaEventRecord(evW, s2);
    // side: stacked z/lpool GEMM (needs gather)
    cudaStreamWaitEvent(s2, evGather, 0);
    gemm_f16<<<dim3(H_ / 128, (2 * B_) / 128), 256, dynSmem, s2>>>(
        fzl, fwh + OFF_WD, fwh + OFF_WL, bl, B_, bd, nullptr, nullptr,
        fxdl, H_, H_, 3, 0);
    cudaEventRecord(evJoin, s2);

    // main: QKV projection (q-compact rows) + attention
    cudaStreamWaitEvent(0, evPack, 0);
    gemm_f16<<<dim3(H3_ / 128, MR_ / 128), 256, dynSmem>>>(
        fgh, fwh + OFF_QKV, nullptr, nullptr, 0, fbqkv, nullptr, nullptr,
        fqkv, H3_, H_, 4, 2);
    attn_kernel<<<B_, 256, ATTN_SMEM>>>();

    // main: Wo projection (+gseq residual via rmap, half out), LN1
    cudaStreamWaitEvent(0, evW, 0);
    gemm_f16<<<dim3(H_ / 128, MR_ / 128), 256, dynSmem>>>(
        fph, fwh + OFF_WO, nullptr, nullptr, 0, bo, fgh, frmap,
        fyh, H_, H_, 1, 1);
    ln_kernel<<<(MR_ + 7) / 8, 256>>>(fyh, ln1g, ln1b, fx1h);

    // main: FFN
    gemm_f16<<<dim3(FF_ / 128, MR_ / 128), 256, dynSmem>>>(
        fx1h, fwh + OFF_W1, nullptr, nullptr, 0, b1, nullptr, nullptr,
        fffh, FF_, H_, 2, 1);
    gemm_f16<<<dim3(H_ / 128, MR_ / 128), 256, dynSmem>>>(
        fffh, fwh + OFF_W2, nullptr, nullptr, 0, b2, fx1h, nullptr,
        fyh, H_, FF_, 1, 1);

    // join, then fused LN2 + pool + gate + output
    cudaStreamWaitEvent(0, evJoin, 0);
    final_kernel<<<B_, 256>>>(fyh, ln2g, ln2b, Wg, bg, out);
}